// round 1
// baseline (speedup 1.0000x reference)
#include <cuda_runtime.h>
#include <cuda_bf16.h>

#define BB 4
#define NN 261888
#define PP 6000
#define NP 2000
#define NBINS 65536
#define CAP 16384
#define NW 94          // ceil(PP/64)
#define NWPAD 96       // padded row (16B aligned)
#define NSEG 64
#define SEGCAP 4096

// ---------------- scratch (device globals; no allocations) ----------------
__device__ unsigned int        g_hist[BB][NBINS];
__device__ unsigned int        g_cursor[BB][NBINS];
__device__ int                 g_thresh[BB];
__device__ unsigned long long  g_cand[BB][CAP];
__device__ __align__(16) float4 g_boxes[BB][PP];
__device__ float               g_area[BB][PP];
__device__ __align__(16) unsigned long long g_supp[BB][PP][NWPAD];

// ---------------- helpers ----------------
__device__ __forceinline__ void cpasync16(unsigned saddr, const void* gaddr) {
    asm volatile("cp.async.cg.shared.global [%0], [%1], 16;\n"
                 :: "r"(saddr), "l"(gaddr) : "memory");
}

// ---------------- K0: zero histogram + thresholds ----------------
__global__ void k_zero() {
    int gid = blockIdx.x * blockDim.x + threadIdx.x;
    if (gid < BB * NBINS) ((unsigned int*)g_hist)[gid] = 0u;
    if (gid < BB) g_thresh[gid] = NBINS;
}

// ---------------- K1: histogram over top-16 bits of score ----------------
__global__ void k_hist(const float* __restrict__ rpn_class) {
    int i = blockIdx.x * blockDim.x + threadIdx.x;
    int b = blockIdx.y;
    if (i >= NN) return;
    float2 sc = *(const float2*)(rpn_class + ((size_t)b * NN + i) * 2);
    unsigned bits = __float_as_uint(sc.y);   // score in [0,1): bits order-preserving
    atomicAdd(&g_hist[b][bits >> 16], 1u);
}

// ---------------- K2: descending exclusive prefix sum; find threshold ----------------
__global__ void k_scan() {
    int b = blockIdx.x, t = threadIdx.x;
    __shared__ unsigned gs[1024];
    unsigned s = 0;
    #pragma unroll 8
    for (int k = 0; k < 64; k++) s += g_hist[b][t * 64 + k];
    gs[t] = s;
    __syncthreads();
    unsigned self = s;
    // inclusive suffix scan (Hillis-Steele)
    for (int off = 1; off < 1024; off <<= 1) {
        unsigned v = (t + off < 1024) ? gs[t + off] : 0u;
        __syncthreads();
        gs[t] += v;
        __syncthreads();
    }
    unsigned run = gs[t] - self;  // elements strictly above this group
    int minbin = NBINS;
    for (int k = 63; k >= 0; k--) {
        int bin = t * 64 + k;
        g_cursor[b][bin] = run;       // base = count in bins > bin
        if (run < PP) minbin = bin;   // descending walk -> ends at smallest bin with base<P
        run += g_hist[b][bin];
    }
    if (minbin < NBINS) atomicMin(&g_thresh[b], minbin);
}

// ---------------- K3: scatter candidates grouped by bin ----------------
__global__ void k_scatter(const float* __restrict__ rpn_class) {
    int i = blockIdx.x * blockDim.x + threadIdx.x;
    int b = blockIdx.y;
    if (i >= NN) return;
    float2 sc = *(const float2*)(rpn_class + ((size_t)b * NN + i) * 2);
    unsigned bits = __float_as_uint(sc.y);
    int bin = bits >> 16;
    if (bin >= g_thresh[b]) {
        unsigned pos = atomicAdd(&g_cursor[b][bin], 1u);
        if (pos < CAP) {
            g_cand[b][pos] = ((unsigned long long)bits << 32)
                           | (unsigned long long)(0xFFFFFFFFu - (unsigned)i);
        }
    }
}

// ---------------- K4: bitonic sort each bin segment (descending) ----------------
__global__ void k_segsort() {
    int b = blockIdx.y;
    int bin = g_thresh[b] + blockIdx.x;
    if (bin >= NBINS) return;
    unsigned cnt = g_hist[b][bin];
    if (cnt <= 1) return;
    unsigned base = g_cursor[b][bin] - cnt;   // cursor is now base+cnt
    __shared__ unsigned long long key[SEGCAP];
    unsigned cc = cnt < (unsigned)SEGCAP ? cnt : (unsigned)SEGCAP;
    unsigned m = 2; while (m < cc) m <<= 1;
    for (unsigned x = threadIdx.x; x < m; x += blockDim.x)
        key[x] = (x < cc) ? g_cand[b][base + x] : 0ull;   // 0 sorts last (keys > 0)
    __syncthreads();
    for (unsigned k = 2; k <= m; k <<= 1) {
        for (unsigned j = k >> 1; j > 0; j >>= 1) {
            for (unsigned x = threadIdx.x; x < m; x += blockDim.x) {
                unsigned l = x ^ j;
                if (l > x) {
                    unsigned long long a = key[x], c = key[l];
                    bool up = ((x & k) == 0);
                    if (up ? (a < c) : (a > c)) { key[x] = c; key[l] = a; }
                }
            }
            __syncthreads();
        }
    }
    for (unsigned x = threadIdx.x; x < cc; x += blockDim.x)
        g_cand[b][base + x] = key[x];
}

// ---------------- K5: decode, clip, normalize top-P boxes ----------------
__global__ void k_decode(const float* __restrict__ rpn_bbox,
                         const float* __restrict__ anchors) {
    int p = blockIdx.x * blockDim.x + threadIdx.x;
    int b = blockIdx.y;
    if (p >= PP) return;
    unsigned long long key = g_cand[b][p];
    unsigned idx = 0xFFFFFFFFu - (unsigned)(key & 0xFFFFFFFFull);
    float4 a = *(const float4*)(anchors + (size_t)idx * 4);
    float4 d = *(const float4*)(rpn_bbox + ((size_t)b * NN + idx) * 4);
    d.x *= 0.1f; d.y *= 0.1f; d.z *= 0.2f; d.w *= 0.2f;
    float h = a.z - a.x, w = a.w - a.y;
    float cy = a.x + 0.5f * h, cx = a.y + 0.5f * w;
    cy = cy + d.x * h;
    cx = cx + d.y * w;
    h = h * expf(d.z);
    w = w * expf(d.w);
    float y1 = cy - 0.5f * h, x1 = cx - 0.5f * w;
    float y2 = cy + 0.5f * h, x2 = cx + 0.5f * w;
    y1 = fminf(fmaxf(y1, 0.f), 1024.f);
    x1 = fminf(fmaxf(x1, 0.f), 1024.f);
    y2 = fminf(fmaxf(y2, 0.f), 1024.f);
    x2 = fminf(fmaxf(x2, 0.f), 1024.f);
    const float inv = 1.0f / 1024.0f;  // exact power of two: same as /1024
    float4 o = make_float4(y1 * inv, x1 * inv, y2 * inv, x2 * inv);
    g_boxes[b][p] = o;
    g_area[b][p] = (o.z - o.x) * (o.w - o.y);
}

// ---------------- K6: suppression bitmask matrix ----------------
__global__ void k_mask() {
    int jb = blockIdx.x, ib = blockIdx.y, b = blockIdx.z;
    int tid = threadIdx.x;
    int i = ib * 64 + tid;
    if (jb < ib) {                 // lower triangle: all bits require j>i -> zero
        if (i < PP) g_supp[b][i][jb] = 0ull;
        return;
    }
    __shared__ float4 bj[64];
    __shared__ float  aj[64];
    int j0 = jb * 64;
    int jt = j0 + tid;
    if (jt < PP) { bj[tid] = g_boxes[b][jt]; aj[tid] = g_area[b][jt]; }
    __syncthreads();
    if (i >= PP) return;
    float4 bi = g_boxes[b][i];
    float  ai = g_area[b][i];
    unsigned long long mask = 0ull;
    int jmax = min(64, PP - j0);
    #pragma unroll 4
    for (int jj = 0; jj < jmax; jj++) {
        int j = j0 + jj;
        if (j <= i) continue;
        float4 bx = bj[jj];
        float iy1 = fmaxf(bi.x, bx.x), ix1 = fmaxf(bi.y, bx.y);
        float iy2 = fminf(bi.z, bx.z), ix2 = fminf(bi.w, bx.w);
        float ih = fmaxf(iy2 - iy1, 0.f), iw = fmaxf(ix2 - ix1, 0.f);
        float inter = ih * iw;
        float uni = ai + aj[jj] - inter;
        if (inter > 0.7f * fmaxf(uni, 1e-8f)) mask |= (1ull << jj);
    }
    g_supp[b][i][jb] = mask;
}

// ---------------- K7: sequential greedy NMS (one warp/batch), cp.async prefetch ----------------
__global__ void k_nms(float* __restrict__ out) {
    int b = blockIdx.x;
    int tid = threadIdx.x;
    __shared__ unsigned long long removed[NW];
    __shared__ __align__(16) unsigned long long ring[8][NWPAD];
    __shared__ __align__(16) float4 ringbox[8];
    float* ob = out + (size_t)b * NP * 4;
    for (int x = tid; x < NP * 4; x += blockDim.x) ob[x] = 0.f;
    for (int x = tid; x < NW; x += blockDim.x) removed[x] = 0ull;
    __syncthreads();
    if (tid >= 32) return;
    int lane = tid;
    const unsigned long long* suppb = &g_supp[b][0][0];

    // prologue: prefetch rows 0..5 (and their boxes)
    for (int r = 0; r < 6; r++) {
        const char* src = (const char*)(suppb + (size_t)r * NWPAD);
        unsigned sdst = (unsigned)__cvta_generic_to_shared(&ring[r][0]);
        for (int c = lane; c < 48; c += 32) cpasync16(sdst + c * 16, src + c * 16);
        if (lane == 0)
            cpasync16((unsigned)__cvta_generic_to_shared(&ringbox[r]),
                      (const void*)&g_boxes[b][r]);
        asm volatile("cp.async.commit_group;\n" ::: "memory");
    }

    int kept = 0;
    for (int i = 0; i < PP; i++) {
        asm volatile("cp.async.wait_group 5;\n" ::: "memory");
        __syncwarp();
        int slot = i & 7;
        unsigned long long rm = removed[i >> 6];
        bool keep = !((rm >> (i & 63)) & 1ull);
        if (keep) {
            if (lane == 0) {
                float4 bx = ringbox[slot];
                *(float4*)(ob + (size_t)kept * 4) = bx;
            }
            #pragma unroll
            for (int c = 0; c < 3; c++) {
                int w = lane + c * 32;
                if (w < NW) removed[w] |= ring[slot][w];
            }
            kept++;
            __syncwarp();
            if (kept == NP) break;
        }
        int nr = i + 6;
        if (nr < PP) {
            int s2 = nr & 7;
            const char* src = (const char*)(suppb + (size_t)nr * NWPAD);
            unsigned sdst = (unsigned)__cvta_generic_to_shared(&ring[s2][0]);
            for (int c = lane; c < 48; c += 32) cpasync16(sdst + c * 16, src + c * 16);
            if (lane == 0)
                cpasync16((unsigned)__cvta_generic_to_shared(&ringbox[s2]),
                          (const void*)&g_boxes[b][nr]);
            asm volatile("cp.async.commit_group;\n" ::: "memory");
        }
    }
    asm volatile("cp.async.wait_group 0;\n" ::: "memory");
}

// ---------------- launch ----------------
extern "C" void kernel_launch(void* const* d_in, const int* in_sizes, int n_in,
                              void* d_out, int out_size) {
    const float* rpn_class = (const float*)d_in[0];
    const float* rpn_bbox  = (const float*)d_in[1];
    const float* anchors   = (const float*)d_in[2];
    float* out = (float*)d_out;

    k_zero<<<(BB * NBINS + 1023) / 1024, 1024>>>();
    dim3 ghist((NN + 255) / 256, BB);
    k_hist<<<ghist, 256>>>(rpn_class);
    k_scan<<<BB, 1024>>>();
    k_scatter<<<ghist, 256>>>(rpn_class);
    k_segsort<<<dim3(NSEG, BB), 256>>>();
    k_decode<<<dim3((PP + 127) / 128, BB), 128>>>(rpn_bbox, anchors);
    k_mask<<<dim3(NW, NW, BB), 64>>>();
    k_nms<<<BB, 128>>>(out);
}